// round 16
// baseline (speedup 1.0000x reference)
#include <cuda_runtime.h>
#include <cuda_fp16.h>
#include <cstdint>

// ---------------------------------------------------------------------------
// Swin shifted-window attention, R16 (single-kernel): R8/R14/R15 structure
// (384 thr / 12 warps, 32x32 GEMM warp tiles, padded stride-200 smem,
// fp16-parked q-phase, pipelined gemm fragments, hoisted weight prefetch)
// with the fp32->fp16 weight conversion folded into the prefetch loads —
// prep_kernel eliminated, one launch per replay.
// ---------------------------------------------------------------------------

#define C       192
#define SHIFT   4
#define SCALE   0.17677669529663687f
#define ASTR    200   // smem row stride in halves (400B, LDSM conflict-free)

__device__ __forceinline__ int tok_to_pix_row(int tok) {
    int bi  = tok >> 16;
    int rr  = tok & 65535;
    int win = rr >> 6, pix = rr & 63;
    int wy = win >> 5, wx = win & 31;
    int py = pix >> 3, px = pix & 7;
    int hh = (wy * 8 + py + SHIFT) & 255;
    int ww = (wx * 8 + px + SHIFT) & 255;
    return ((bi << 8 | hh) << 8 | ww) * C;
}

__device__ __forceinline__ uint32_t smem_u32(const void* p) {
    return (uint32_t)__cvta_generic_to_shared(p);
}
__device__ __forceinline__ void ldsm4(uint32_t& r0, uint32_t& r1, uint32_t& r2,
                                      uint32_t& r3, uint32_t a) {
    asm volatile("ldmatrix.sync.aligned.m8n8.x4.shared.b16 {%0,%1,%2,%3},[%4];\n"
                 : "=r"(r0), "=r"(r1), "=r"(r2), "=r"(r3) : "r"(a));
}
__device__ __forceinline__ void ldsm4t(uint32_t& r0, uint32_t& r1, uint32_t& r2,
                                       uint32_t& r3, uint32_t a) {
    asm volatile("ldmatrix.sync.aligned.m8n8.x4.trans.shared.b16 {%0,%1,%2,%3},[%4];\n"
                 : "=r"(r0), "=r"(r1), "=r"(r2), "=r"(r3) : "r"(a));
}
__device__ __forceinline__ void mma16816(float* c, const uint32_t* a, const uint32_t* b) {
    asm volatile(
        "mma.sync.aligned.m16n8k16.row.col.f32.f16.f16.f32 "
        "{%0,%1,%2,%3},{%4,%5,%6,%7},{%8,%9},{%0,%1,%2,%3};\n"
        : "+f"(c[0]), "+f"(c[1]), "+f"(c[2]), "+f"(c[3])
        : "r"(a[0]), "r"(a[1]), "r"(a[2]), "r"(a[3]), "r"(b[0]), "r"(b[1]));
}

// ---------------------------------------------------------------------------
// helpers (384 threads)
// ---------------------------------------------------------------------------
__device__ __forceinline__ void stage_input(const float* __restrict__ src,
                                            __half* dst, int m0, int tid)
{
    #pragma unroll
    for (int t = 0; t < 8; ++t) {
        int i = tid + t * 384;          // 3072 tasks of 8 floats
        int row = i / 24, off = (i % 24) * 8;
        const float* p = src + tok_to_pix_row(m0 + row) + off;
        float4 f0 = *(const float4*)p;
        float4 f1 = *(const float4*)(p + 4);
        __half2 hh[4] = { __floats2half2_rn(f0.x, f0.y), __floats2half2_rn(f0.z, f0.w),
                          __floats2half2_rn(f1.x, f1.y), __floats2half2_rn(f1.z, f1.w) };
        *(uint4*)&dst[row * ASTR + off] = *(uint4*)hh;
    }
}

// weight group prefetch: 96 rows x 192 values, loaded fp32 + converted to
// fp16 in registers (2304 8-half tasks, 6 per thread)
__device__ __forceinline__ void pf_load(uint4 pf[6], const float* __restrict__ w, int tid)
{
    #pragma unroll
    for (int t = 0; t < 6; ++t) {
        int i = tid + t * 384;
        int row = i / 24, off = (i % 24) * 8;
        const float* p = w + (size_t)row * C + off;
        float4 f0 = *(const float4*)p;
        float4 f1 = *(const float4*)(p + 4);
        __half2 hh[4] = { __floats2half2_rn(f0.x, f0.y), __floats2half2_rn(f0.z, f0.w),
                          __floats2half2_rn(f1.x, f1.y), __floats2half2_rn(f1.z, f1.w) };
        pf[t] = *(uint4*)hh;
    }
}
__device__ __forceinline__ void pf_store(__half* dst, const uint4 pf[6], int tid)
{
    #pragma unroll
    for (int t = 0; t < 6; ++t) {
        int i = tid + t * 384;
        int row = i / 24, off = (i % 24) * 8;
        *(uint4*)&dst[row * ASTR + off] = pf[t];
    }
}

// load one k-step's A/B fragments for the 32x32 warp tile
__device__ __forceinline__ void load_frags(const __half* As, const __half* Bs, int kk,
                                           int lane, int wm, int wn,
                                           uint32_t afr[2][4], uint32_t bfr[4][2])
{
    #pragma unroll
    for (int mt = 0; mt < 2; ++mt) {
        uint32_t aa = smem_u32(&As[(wm + 16 * mt + (lane & 15)) * ASTR
                                   + kk + 8 * (lane >> 4)]);
        ldsm4(afr[mt][0], afr[mt][1], afr[mt][2], afr[mt][3], aa);
    }
    #pragma unroll
    for (int g = 0; g < 2; ++g) {
        int m = lane >> 3;
        uint32_t ba = smem_u32(&Bs[(wn + 16 * g + (lane & 7) + 8 * (m >> 1)) * ASTR
                                   + kk + 8 * (m & 1)]);
        ldsm4(bfr[2*g][0], bfr[2*g][1], bfr[2*g+1][0], bfr[2*g+1][1], ba);
    }
}

// 128x96 GEMM over K=192: warp tile 32x32 (12 warps = 4m x 3n),
// software-pipelined fragment double-buffering.
__device__ __forceinline__ void gemm_group(const __half* As, const __half* Bs,
                                           int lane, int wm, int wn, float acc[2][4][4])
{
    uint32_t afr[2][2][4], bfr[2][4][2];
    load_frags(As, Bs, 0, lane, wm, wn, afr[0], bfr[0]);
    #pragma unroll
    for (int i = 0; i < 12; ++i) {
        const int cur = i & 1;
        if (i < 11)
            load_frags(As, Bs, (i + 1) * 16, lane, wm, wn, afr[cur ^ 1], bfr[cur ^ 1]);
        #pragma unroll
        for (int mt = 0; mt < 2; ++mt)
            #pragma unroll
            for (int nt = 0; nt < 4; ++nt)
                mma16816(acc[mt][nt], afr[cur][mt], bfr[cur][nt]);
    }
}

// epilogue straight to smem: fp16 + bias, bias pre-offset (col in [0,96))
__device__ __forceinline__ void epi_smem(__half* dst, int colbase,
                                         const float* __restrict__ bias,
                                         int lane, int wm, int wn, float acc[2][4][4])
{
    #pragma unroll
    for (int nt = 0; nt < 4; ++nt) {
        int col = wn + 8 * nt + 2 * (lane & 3);
        float b0 = bias[col], b1 = bias[col + 1];
        int cd = colbase + col;
        #pragma unroll
        for (int mt = 0; mt < 2; ++mt) {
            int r0 = wm + 16 * mt + (lane >> 2);
            *(__half2*)&dst[r0 * ASTR + cd] =
                __floats2half2_rn(acc[mt][nt][0] + b0, acc[mt][nt][1] + b1);
            *(__half2*)&dst[(r0 + 8) * ASTR + cd] =
                __floats2half2_rn(acc[mt][nt][2] + b0, acc[mt][nt][3] + b1);
        }
    }
}

// park biased result as fp16 in registers (16 half2)
__device__ __forceinline__ void epi_park(uint32_t park[16],
                                         const float* __restrict__ bias,
                                         int lane, int wn, float acc[2][4][4])
{
    #pragma unroll
    for (int nt = 0; nt < 4; ++nt) {
        int col = wn + 8 * nt + 2 * (lane & 3);
        float b0 = bias[col], b1 = bias[col + 1];
        #pragma unroll
        for (int mt = 0; mt < 2; ++mt) {
            __half2 h0 = __floats2half2_rn(acc[mt][nt][0] + b0, acc[mt][nt][1] + b1);
            __half2 h1 = __floats2half2_rn(acc[mt][nt][2] + b0, acc[mt][nt][3] + b1);
            park[nt * 4 + mt * 2 + 0] = *(uint32_t*)&h0;
            park[nt * 4 + mt * 2 + 1] = *(uint32_t*)&h1;
        }
    }
}
__device__ __forceinline__ void epi_unpark(__half* dst, int colbase,
                                           int lane, int wm, int wn,
                                           const uint32_t park[16])
{
    #pragma unroll
    for (int nt = 0; nt < 4; ++nt) {
        int cd = colbase + wn + 8 * nt + 2 * (lane & 3);
        #pragma unroll
        for (int mt = 0; mt < 2; ++mt) {
            int r0 = wm + 16 * mt + (lane >> 2);
            *(uint32_t*)&dst[r0 * ASTR + cd]       = park[nt * 4 + mt * 2 + 0];
            *(uint32_t*)&dst[(r0 + 8) * ASTR + cd] = park[nt * 4 + mt * 2 + 1];
        }
    }
}

// one warp: 32 query rows x 64 keys for one (window, head); O overwrites Q
__device__ __forceinline__ void attn_task32(__half* Qs, const __half* Ks, const __half* Vs,
                                            const float* rl, int w64, int hc, int rt,
                                            bool maskY, bool maskX, int lane)
{
    const int rbase = w64 + 32 * rt;

    float c[2][8][4] = {};
    #pragma unroll
    for (int kc = 0; kc < 32; kc += 16) {
        uint32_t qf[2][4], kf[8][2];
        #pragma unroll
        for (int mt = 0; mt < 2; ++mt) {
            uint32_t aa = smem_u32(&Qs[(rbase + 16 * mt + (lane & 15)) * ASTR
                                       + hc + kc + 8 * (lane >> 4)]);
            ldsm4(qf[mt][0], qf[mt][1], qf[mt][2], qf[mt][3], aa);
        }
        #pragma unroll
        for (int g = 0; g < 4; ++g) {
            int m = lane >> 3;
            uint32_t ba = smem_u32(&Ks[(w64 + 16 * g + (lane & 7) + 8 * (m >> 1)) * ASTR
                                       + hc + kc + 8 * (m & 1)]);
            ldsm4(kf[2*g][0], kf[2*g][1], kf[2*g+1][0], kf[2*g+1][1], ba);
        }
        #pragma unroll
        for (int mt = 0; mt < 2; ++mt)
            #pragma unroll
            for (int nt = 0; nt < 8; ++nt)
                mma16816(c[mt][nt], qf[mt], kf[nt]);
    }

    const int qx0 = 2 * (lane & 3), qx1 = qx0 + 1;
    float i1[2], i2[2];
    #pragma unroll
    for (int mt = 0; mt < 2; ++mt) {
        int r1 = 32 * rt + 16 * mt + (lane >> 2), r2 = r1 + 8;
        int r1y = r1 >> 3, r1x = r1 & 7, r2y = r2 >> 3;   // r2x == r1x
        #pragma unroll
        for (int nt = 0; nt < 8; ++nt) {
            bool mY1 = maskY && ((r1y < 4) != (nt < 4));
            bool mY2 = maskY && ((r2y < 4) != (nt < 4));
            bool mX0 = maskX && ((r1x < 4) != (qx0 < 4));
            bool mX1 = maskX && ((r1x < 4) != (qx1 < 4));
            float v0 = c[mt][nt][0] * SCALE + rl[(r1y - nt + 7) * 15 + (r1x - qx0 + 7)];
            float v1 = c[mt][nt][1] * SCALE + rl[(r1y - nt + 7) * 15 + (r1x - qx1 + 7)];
            float v2 = c[mt][nt][2] * SCALE + rl[(r2y - nt + 7) * 15 + (r1x - qx0 + 7)];
            float v3 = c[mt][nt][3] * SCALE + rl[(r2y - nt + 7) * 15 + (r1x - qx1 + 7)];
            c[mt][nt][0] = (mY1 || mX0) ? -1e30f : v0;
            c[mt][nt][1] = (mY1 || mX1) ? -1e30f : v1;
            c[mt][nt][2] = (mY2 || mX0) ? -1e30f : v2;
            c[mt][nt][3] = (mY2 || mX1) ? -1e30f : v3;
        }
        float mx1 = -1e30f, mx2 = -1e30f;
        #pragma unroll
        for (int nt = 0; nt < 8; ++nt) {
            mx1 = fmaxf(mx1, fmaxf(c[mt][nt][0], c[mt][nt][1]));
            mx2 = fmaxf(mx2, fmaxf(c[mt][nt][2], c[mt][nt][3]));
        }
        mx1 = fmaxf(mx1, __shfl_xor_sync(0xffffffffu, mx1, 1));
        mx1 = fmaxf(mx1, __shfl_xor_sync(0xffffffffu, mx1, 2));
        mx2 = fmaxf(mx2, __shfl_xor_sync(0xffffffffu, mx2, 1));
        mx2 = fmaxf(mx2, __shfl_xor_sync(0xffffffffu, mx2, 2));
        float s1 = 0.f, s2 = 0.f;
        #pragma unroll
        for (int nt = 0; nt < 8; ++nt) {
            c[mt][nt][0] = __expf(c[mt][nt][0] - mx1); s1 += c[mt][nt][0];
            c[mt][nt][1] = __expf(c[mt][nt][1] - mx1); s1 += c[mt][nt][1];
            c[mt][nt][2] = __expf(c[mt][nt][2] - mx2); s2 += c[mt][nt][2];
            c[mt][nt][3] = __expf(c[mt][nt][3] - mx2); s2 += c[mt][nt][3];
        }
        s1 += __shfl_xor_sync(0xffffffffu, s1, 1);
        s1 += __shfl_xor_sync(0xffffffffu, s1, 2);
        s2 += __shfl_xor_sync(0xffffffffu, s2, 1);
        s2 += __shfl_xor_sync(0xffffffffu, s2, 2);
        i1[mt] = 1.f / s1; i2[mt] = 1.f / s2;
    }

    uint32_t p[2][4][4];
    #pragma unroll
    for (int mt = 0; mt < 2; ++mt)
        #pragma unroll
        for (int kt = 0; kt < 4; ++kt) {
            __half2 h0 = __floats2half2_rn(c[mt][2*kt  ][0] * i1[mt], c[mt][2*kt  ][1] * i1[mt]);
            __half2 h1 = __floats2half2_rn(c[mt][2*kt  ][2] * i2[mt], c[mt][2*kt  ][3] * i2[mt]);
            __half2 h2 = __floats2half2_rn(c[mt][2*kt+1][0] * i1[mt], c[mt][2*kt+1][1] * i1[mt]);
            __half2 h3 = __floats2half2_rn(c[mt][2*kt+1][2] * i2[mt], c[mt][2*kt+1][3] * i2[mt]);
            p[mt][kt][0] = *(uint32_t*)&h0; p[mt][kt][1] = *(uint32_t*)&h1;
            p[mt][kt][2] = *(uint32_t*)&h2; p[mt][kt][3] = *(uint32_t*)&h3;
        }

    float o[2][4][4] = {};
    #pragma unroll
    for (int kt = 0; kt < 4; ++kt) {
        uint32_t vf[4][2];
        #pragma unroll
        for (int g = 0; g < 2; ++g) {
            int m = lane >> 3;
            uint32_t va = smem_u32(&Vs[(w64 + 16 * kt + (lane & 7) + 8 * (m & 1)) * ASTR
                                       + hc + 16 * g + 8 * (m >> 1)]);
            ldsm4t(vf[2*g][0], vf[2*g][1], vf[2*g+1][0], vf[2*g+1][1], va);
        }
        #pragma unroll
        for (int mt = 0; mt < 2; ++mt)
            #pragma unroll
            for (int nt = 0; nt < 4; ++nt)
                mma16816(o[mt][nt], p[mt][kt], vf[nt]);
    }

    #pragma unroll
    for (int mt = 0; mt < 2; ++mt) {
        int r1 = rbase + 16 * mt + (lane >> 2), r2 = r1 + 8;
        #pragma unroll
        for (int nt = 0; nt < 4; ++nt) {
            int cc = hc + 8 * nt + 2 * (lane & 3);
            *(__half2*)&Qs[r1 * ASTR + cc] = __floats2half2_rn(o[mt][nt][0], o[mt][nt][1]);
            *(__half2*)&Qs[r2 * ASTR + cc] = __floats2half2_rn(o[mt][nt][2], o[mt][nt][3]);
        }
    }
}

// ---------------------------------------------------------------------------
// The fused kernel. grid(1024), 384 threads (12 warps: 4m x 3n of 32x32).
// smem (halves): Qs@0, Ks@25600, Vs@51200, Bs@76800 (96x200), rel@96000.
// ---------------------------------------------------------------------------
#define SM_K 25600
#define SM_V 51200
#define SM_B 76800
#define SM_R 96000
#define FUSED_SMEM (96000 * 2 + 5400)

__global__ __launch_bounds__(384, 1)
void fused_kernel(const float* __restrict__ xin, const float* __restrict__ bin,
                  const float* __restrict__ w_qkv, const float* __restrict__ b_qkv,
                  const float* __restrict__ w_qkv_b, const float* __restrict__ b_qkv_b,
                  const float* __restrict__ rel,
                  const float* __restrict__ w_out, const float* __restrict__ b_out,
                  float* __restrict__ out)
{
    extern __shared__ __half sm[];
    __half* Qs  = sm;
    __half* Ks  = sm + SM_K;
    __half* Vs  = sm + SM_V;
    __half* Bsm = sm + SM_B;
    float*  rel_s = (float*)(sm + SM_R);

    const int tid = threadIdx.x, warp = tid >> 5, lane = tid & 31;
    const int m0 = blockIdx.x * 128;
    const int wm = (warp / 3) * 32;
    const int wn = (warp % 3) * 32;

    // fp32 weight group pointers in consumption order: K0,K1,V0,V1,Q0,Q1,P0,P1
    const float* W[8] = {
        w_qkv + (size_t)192 * C, w_qkv + (size_t)288 * C,
        w_qkv + (size_t)384 * C, w_qkv + (size_t)480 * C,
        w_qkv_b, w_qkv_b + (size_t)96 * C,
        w_out,  w_out  + (size_t)96 * C };

    uint4 pf[6];

    for (int i = tid; i < 1350; i += 384) rel_s[i] = rel[i];

    // ---- stage x, prefetch+convert first weights ----
    stage_input(xin, Qs, m0, tid);
    pf_load(pf, W[0], tid);
    __syncthreads();

    // ---- K, V (4 groups of 96); next-group LDG issued before the barrier ----
    #pragma unroll
    for (int s = 0; s < 4; ++s) {
        pf_store(Bsm, pf, tid);
        pf_load(pf, W[s + 1], tid);             // hoisted: overlaps barrier + gemm
        __syncthreads();
        float acc[2][4][4] = {};
        gemm_group(Qs, Bsm, lane, wm, wn, acc);
        epi_smem((s < 2) ? Ks : Vs, (s & 1) * 96,
                 b_qkv + 192 + s * 96, lane, wm, wn, acc);
        __syncthreads();
    }

    // ---- stage b, compute Q (fp16-parked, in-place store after sync) ----
    stage_input(bin, Qs, m0, tid);
    __syncthreads();
    {
        uint32_t parkA[16], parkB[16];
        pf_store(Bsm, pf, tid);                 // W4 = Q0
        pf_load(pf, W[5], tid);                 // hoisted
        __syncthreads();
        {
            float acc[2][4][4] = {};
            gemm_group(Qs, Bsm, lane, wm, wn, acc);
            epi_park(parkA, b_qkv_b, lane, wn, acc);
        }
        __syncthreads();
        pf_store(Bsm, pf, tid);                 // W5 = Q1
        pf_load(pf, W[6], tid);                 // hoisted
        __syncthreads();
        {
            float acc[2][4][4] = {};
            gemm_group(Qs, Bsm, lane, wm, wn, acc);
            epi_park(parkB, b_qkv_b + 96, lane, wn, acc);
        }
        __syncthreads();                        // all Qs(b) reads done
        epi_unpark(Qs, 0,  lane, wm, wn, parkA);
        epi_unpark(Qs, 96, lane, wm, wn, parkB);
    }
    __syncthreads();

    // ---- attention: 24 tasks (2 win x 6 heads x 2 row-halves), 12 warps ----
    {
        const int gw0 = blockIdx.x * 2;
        #pragma unroll
        for (int task = warp; task < 24; task += 12) {
            int pair = task >> 1, rt = task & 1;
            int win  = (pair >= 6) ? 1 : 0;
            int head = pair - win * 6;
            int wimg = (gw0 + win) & 1023;
            attn_task32(Qs, Ks, Vs, rel_s + head * 225, win * 64, head * 32, rt,
                        (wimg >> 5) == 31, (wimg & 31) == 31, lane);
        }
    }

    // ---- output projection + scatter ----
    int orow[2][2];
    #pragma unroll
    for (int mt = 0; mt < 2; ++mt) {
        int r0 = m0 + wm + 16 * mt + (lane >> 2);
        orow[mt][0] = tok_to_pix_row(r0);
        orow[mt][1] = tok_to_pix_row(r0 + 8);
    }
    #pragma unroll
    for (int g = 0; g < 2; ++g) {
        pf_store(Bsm, pf, tid);                 // W6 / W7
        if (g == 0) pf_load(pf, W[7], tid);     // hoisted
        __syncthreads();                        // O visible + B ready
        float acc[2][4][4] = {};
        gemm_group(Qs, Bsm, lane, wm, wn, acc);
        #pragma unroll
        for (int nt = 0; nt < 4; ++nt) {
            int colg = g * 96 + wn + 8 * nt + 2 * (lane & 3);
            float b0 = b_out[colg], b1 = b_out[colg + 1];
            #pragma unroll
            for (int mt = 0; mt < 2; ++mt) {
                *(float2*)(out + orow[mt][0] + colg) =
                    make_float2(acc[mt][nt][0] + b0, acc[mt][nt][1] + b1);
                *(float2*)(out + orow[mt][1] + colg) =
                    make_float2(acc[mt][nt][2] + b0, acc[mt][nt][3] + b1);
            }
        }
        __syncthreads();                        // Bsm reads done before next store
    }
}

// ---------------------------------------------------------------------------
extern "C" void kernel_launch(void* const* d_in, const int* in_sizes, int n_in,
                              void* d_out, int out_size)
{
    const float* x        = (const float*)d_in[0];
    const float* b        = (const float*)d_in[1];
    const float* w_qkv    = (const float*)d_in[2];
    const float* b_qkv    = (const float*)d_in[3];
    const float* w_qkv_b  = (const float*)d_in[4];
    const float* b_qkv_b  = (const float*)d_in[5];
    const float* rel      = (const float*)d_in[6];
    const float* w_out    = (const float*)d_in[7];
    const float* b_out    = (const float*)d_in[8];
    float* out = (float*)d_out;

    cudaFuncSetAttribute(fused_kernel, cudaFuncAttributeMaxDynamicSharedMemorySize,
                         FUSED_SMEM);

    fused_kernel<<<1024, 384, FUSED_SMEM>>>(x, b, w_qkv, b_qkv, w_qkv_b, b_qkv_b,
                                            rel, w_out, b_out, out);
}

// round 17
// speedup vs baseline: 1.0671x; 1.0671x over previous
#include <cuda_runtime.h>
#include <cuda_fp16.h>
#include <cstdint>

// ---------------------------------------------------------------------------
// Swin shifted-window attention, R17: R14 structure (384 thr / 12 warps,
// 32x32 GEMM warp tiles, padded stride-200 smem, register weight prefetch,
// fp16-parked q-phase, pipelined gemm fragments) + vectorized prep kernel +
// programmatic dependent launch (fused prologue overlaps prep).
// ---------------------------------------------------------------------------

#define C       192
#define SHIFT   4
#define SCALE   0.17677669529663687f
#define ASTR    200   // smem row stride in halves (400B, LDSM conflict-free)

__device__ __half gw_qkv [576 * C];
__device__ __half gw_qkvb[576 * C];
__device__ __half gw_out [C * C];

__device__ __forceinline__ int tok_to_pix_row(int tok) {
    int bi  = tok >> 16;
    int rr  = tok & 65535;
    int win = rr >> 6, pix = rr & 63;
    int wy = win >> 5, wx = win & 31;
    int py = pix >> 3, px = pix & 7;
    int hh = (wy * 8 + py + SHIFT) & 255;
    int ww = (wx * 8 + px + SHIFT) & 255;
    return ((bi << 8 | hh) << 8 | ww) * C;
}

__device__ __forceinline__ uint32_t smem_u32(const void* p) {
    return (uint32_t)__cvta_generic_to_shared(p);
}
__device__ __forceinline__ void ldsm4(uint32_t& r0, uint32_t& r1, uint32_t& r2,
                                      uint32_t& r3, uint32_t a) {
    asm volatile("ldmatrix.sync.aligned.m8n8.x4.shared.b16 {%0,%1,%2,%3},[%4];\n"
                 : "=r"(r0), "=r"(r1), "=r"(r2), "=r"(r3) : "r"(a));
}
__device__ __forceinline__ void ldsm4t(uint32_t& r0, uint32_t& r1, uint32_t& r2,
                                       uint32_t& r3, uint32_t a) {
    asm volatile("ldmatrix.sync.aligned.m8n8.x4.trans.shared.b16 {%0,%1,%2,%3},[%4];\n"
                 : "=r"(r0), "=r"(r1), "=r"(r2), "=r"(r3) : "r"(a));
}
__device__ __forceinline__ void mma16816(float* c, const uint32_t* a, const uint32_t* b) {
    asm volatile(
        "mma.sync.aligned.m16n8k16.row.col.f32.f16.f16.f32 "
        "{%0,%1,%2,%3},{%4,%5,%6,%7},{%8,%9},{%0,%1,%2,%3};\n"
        : "+f"(c[0]), "+f"(c[1]), "+f"(c[2]), "+f"(c[3])
        : "r"(a[0]), "r"(a[1]), "r"(a[2]), "r"(a[3]), "r"(b[0]), "r"(b[1]));
}

// ---------------------------------------------------------------------------
// Kernel 0: weight conversion fp32 -> fp16, vectorized (4 elems/thread).
// ---------------------------------------------------------------------------
__global__ __launch_bounds__(256) void prep_kernel(
    const float* __restrict__ w_qkv, const float* __restrict__ w_qkv_b,
    const float* __restrict__ w_out)
{
    int i = (blockIdx.x * 256 + threadIdx.x) * 4;
    if (i < 576 * C) {
        float4 a = *(const float4*)(w_qkv + i);
        float4 b = *(const float4*)(w_qkv_b + i);
        __half2 ha[2] = { __floats2half2_rn(a.x, a.y), __floats2half2_rn(a.z, a.w) };
        __half2 hb[2] = { __floats2half2_rn(b.x, b.y), __floats2half2_rn(b.z, b.w) };
        *(uint2*)&gw_qkv [i] = *(uint2*)ha;
        *(uint2*)&gw_qkvb[i] = *(uint2*)hb;
    }
    if (i < C * C) {
        float4 c = *(const float4*)(w_out + i);
        __half2 hc[2] = { __floats2half2_rn(c.x, c.y), __floats2half2_rn(c.z, c.w) };
        *(uint2*)&gw_out[i] = *(uint2*)hc;
    }
}

// ---------------------------------------------------------------------------
// helpers (384 threads)
// ---------------------------------------------------------------------------
__device__ __forceinline__ void stage_input(const float* __restrict__ src,
                                            __half* dst, int m0, int tid)
{
    #pragma unroll
    for (int t = 0; t < 8; ++t) {
        int i = tid + t * 384;          // 3072 tasks of 8 floats
        int row = i / 24, off = (i % 24) * 8;
        const float* p = src + tok_to_pix_row(m0 + row) + off;
        float4 f0 = *(const float4*)p;
        float4 f1 = *(const float4*)(p + 4);
        __half2 hh[4] = { __floats2half2_rn(f0.x, f0.y), __floats2half2_rn(f0.z, f0.w),
                          __floats2half2_rn(f1.x, f1.y), __floats2half2_rn(f1.z, f1.w) };
        *(uint4*)&dst[row * ASTR + off] = *(uint4*)hh;
    }
}

// weight group prefetch: 96 rows x 192 halves = 2304 uint4, 6 per thread
__device__ __forceinline__ void pf_load(uint4 pf[6], const __half* __restrict__ w, int tid)
{
    #pragma unroll
    for (int t = 0; t < 6; ++t) {
        int i = tid + t * 384;
        int row = i / 24, off = (i % 24) * 8;
        pf[t] = *(const uint4*)(w + (size_t)row * C + off);
    }
}
__device__ __forceinline__ void pf_store(__half* dst, const uint4 pf[6], int tid)
{
    #pragma unroll
    for (int t = 0; t < 6; ++t) {
        int i = tid + t * 384;
        int row = i / 24, off = (i % 24) * 8;
        *(uint4*)&dst[row * ASTR + off] = pf[t];
    }
}

// load one k-step's A/B fragments for the 32x32 warp tile
__device__ __forceinline__ void load_frags(const __half* As, const __half* Bs, int kk,
                                           int lane, int wm, int wn,
                                           uint32_t afr[2][4], uint32_t bfr[4][2])
{
    #pragma unroll
    for (int mt = 0; mt < 2; ++mt) {
        uint32_t aa = smem_u32(&As[(wm + 16 * mt + (lane & 15)) * ASTR
                                   + kk + 8 * (lane >> 4)]);
        ldsm4(afr[mt][0], afr[mt][1], afr[mt][2], afr[mt][3], aa);
    }
    #pragma unroll
    for (int g = 0; g < 2; ++g) {
        int m = lane >> 3;
        uint32_t ba = smem_u32(&Bs[(wn + 16 * g + (lane & 7) + 8 * (m >> 1)) * ASTR
                                   + kk + 8 * (m & 1)]);
        ldsm4(bfr[2*g][0], bfr[2*g][1], bfr[2*g+1][0], bfr[2*g+1][1], ba);
    }
}

// 128x96 GEMM over K=192: warp tile 32x32 (12 warps = 4m x 3n),
// software-pipelined fragment double-buffering.
__device__ __forceinline__ void gemm_group(const __half* As, const __half* Bs,
                                           int lane, int wm, int wn, float acc[2][4][4])
{
    uint32_t afr[2][2][4], bfr[2][4][2];
    load_frags(As, Bs, 0, lane, wm, wn, afr[0], bfr[0]);
    #pragma unroll
    for (int i = 0; i < 12; ++i) {
        const int cur = i & 1;
        if (i < 11)
            load_frags(As, Bs, (i + 1) * 16, lane, wm, wn, afr[cur ^ 1], bfr[cur ^ 1]);
        #pragma unroll
        for (int mt = 0; mt < 2; ++mt)
            #pragma unroll
            for (int nt = 0; nt < 4; ++nt)
                mma16816(acc[mt][nt], afr[cur][mt], bfr[cur][nt]);
    }
}

// epilogue straight to smem: fp16 + bias, bias pre-offset (col in [0,96))
__device__ __forceinline__ void epi_smem(__half* dst, int colbase,
                                         const float* __restrict__ bias,
                                         int lane, int wm, int wn, float acc[2][4][4])
{
    #pragma unroll
    for (int nt = 0; nt < 4; ++nt) {
        int col = wn + 8 * nt + 2 * (lane & 3);
        float b0 = bias[col], b1 = bias[col + 1];
        int cd = colbase + col;
        #pragma unroll
        for (int mt = 0; mt < 2; ++mt) {
            int r0 = wm + 16 * mt + (lane >> 2);
            *(__half2*)&dst[r0 * ASTR + cd] =
                __floats2half2_rn(acc[mt][nt][0] + b0, acc[mt][nt][1] + b1);
            *(__half2*)&dst[(r0 + 8) * ASTR + cd] =
                __floats2half2_rn(acc[mt][nt][2] + b0, acc[mt][nt][3] + b1);
        }
    }
}

// park biased result as fp16 in registers (16 half2)
__device__ __forceinline__ void epi_park(uint32_t park[16],
                                         const float* __restrict__ bias,
                                         int lane, int wn, float acc[2][4][4])
{
    #pragma unroll
    for (int nt = 0; nt < 4; ++nt) {
        int col = wn + 8 * nt + 2 * (lane & 3);
        float b0 = bias[col], b1 = bias[col + 1];
        #pragma unroll
        for (int mt = 0; mt < 2; ++mt) {
            __half2 h0 = __floats2half2_rn(acc[mt][nt][0] + b0, acc[mt][nt][1] + b1);
            __half2 h1 = __floats2half2_rn(acc[mt][nt][2] + b0, acc[mt][nt][3] + b1);
            park[nt * 4 + mt * 2 + 0] = *(uint32_t*)&h0;
            park[nt * 4 + mt * 2 + 1] = *(uint32_t*)&h1;
        }
    }
}
__device__ __forceinline__ void epi_unpark(__half* dst, int colbase,
                                           int lane, int wm, int wn,
                                           const uint32_t park[16])
{
    #pragma unroll
    for (int nt = 0; nt < 4; ++nt) {
        int cd = colbase + wn + 8 * nt + 2 * (lane & 3);
        #pragma unroll
        for (int mt = 0; mt < 2; ++mt) {
            int r0 = wm + 16 * mt + (lane >> 2);
            *(uint32_t*)&dst[r0 * ASTR + cd]       = park[nt * 4 + mt * 2 + 0];
            *(uint32_t*)&dst[(r0 + 8) * ASTR + cd] = park[nt * 4 + mt * 2 + 1];
        }
    }
}

// one warp: 32 query rows x 64 keys for one (window, head); O overwrites Q
__device__ __forceinline__ void attn_task32(__half* Qs, const __half* Ks, const __half* Vs,
                                            const float* rl, int w64, int hc, int rt,
                                            bool maskY, bool maskX, int lane)
{
    const int rbase = w64 + 32 * rt;

    float c[2][8][4] = {};
    #pragma unroll
    for (int kc = 0; kc < 32; kc += 16) {
        uint32_t qf[2][4], kf[8][2];
        #pragma unroll
        for (int mt = 0; mt < 2; ++mt) {
            uint32_t aa = smem_u32(&Qs[(rbase + 16 * mt + (lane & 15)) * ASTR
                                       + hc + kc + 8 * (lane >> 4)]);
            ldsm4(qf[mt][0], qf[mt][1], qf[mt][2], qf[mt][3], aa);
        }
        #pragma unroll
        for (int g = 0; g < 4; ++g) {
            int m = lane >> 3;
            uint32_t ba = smem_u32(&Ks[(w64 + 16 * g + (lane & 7) + 8 * (m >> 1)) * ASTR
                                       + hc + kc + 8 * (m & 1)]);
            ldsm4(kf[2*g][0], kf[2*g][1], kf[2*g+1][0], kf[2*g+1][1], ba);
        }
        #pragma unroll
        for (int mt = 0; mt < 2; ++mt)
            #pragma unroll
            for (int nt = 0; nt < 8; ++nt)
                mma16816(c[mt][nt], qf[mt], kf[nt]);
    }

    const int qx0 = 2 * (lane & 3), qx1 = qx0 + 1;
    float i1[2], i2[2];
    #pragma unroll
    for (int mt = 0; mt < 2; ++mt) {
        int r1 = 32 * rt + 16 * mt + (lane >> 2), r2 = r1 + 8;
        int r1y = r1 >> 3, r1x = r1 & 7, r2y = r2 >> 3;   // r2x == r1x
        #pragma unroll
        for (int nt = 0; nt < 8; ++nt) {
            bool mY1 = maskY && ((r1y < 4) != (nt < 4));
            bool mY2 = maskY && ((r2y < 4) != (nt < 4));
            bool mX0 = maskX && ((r1x < 4) != (qx0 < 4));
            bool mX1 = maskX && ((r1x < 4) != (qx1 < 4));
            float v0 = c[mt][nt][0] * SCALE + rl[(r1y - nt + 7) * 15 + (r1x - qx0 + 7)];
            float v1 = c[mt][nt][1] * SCALE + rl[(r1y - nt + 7) * 15 + (r1x - qx1 + 7)];
            float v2 = c[mt][nt][2] * SCALE + rl[(r2y - nt + 7) * 15 + (r1x - qx0 + 7)];
            float v3 = c[mt][nt][3] * SCALE + rl[(r2y - nt + 7) * 15 + (r1x - qx1 + 7)];
            c[mt][nt][0] = (mY1 || mX0) ? -1e30f : v0;
            c[mt][nt][1] = (mY1 || mX1) ? -1e30f : v1;
            c[mt][nt][2] = (mY2 || mX0) ? -1e30f : v2;
            c[mt][nt][3] = (mY2 || mX1) ? -1e30f : v3;
        }
        float mx1 = -1e30f, mx2 = -1e30f;
        #pragma unroll
        for (int nt = 0; nt < 8; ++nt) {
            mx1 = fmaxf(mx1, fmaxf(c[mt][nt][0], c[mt][nt][1]));
            mx2 = fmaxf(mx2, fmaxf(c[mt][nt][2], c[mt][nt][3]));
        }
        mx1 = fmaxf(mx1, __shfl_xor_sync(0xffffffffu, mx1, 1));
        mx1 = fmaxf(mx1, __shfl_xor_sync(0xffffffffu, mx1, 2));
        mx2 = fmaxf(mx2, __shfl_xor_sync(0xffffffffu, mx2, 1));
        mx2 = fmaxf(mx2, __shfl_xor_sync(0xffffffffu, mx2, 2));
        float s1 = 0.f, s2 = 0.f;
        #pragma unroll
        for (int nt = 0; nt < 8; ++nt) {
            c[mt][nt][0] = __expf(c[mt][nt][0] - mx1); s1 += c[mt][nt][0];
            c[mt][nt][1] = __expf(c[mt][nt][1] - mx1); s1 += c[mt][nt][1];
            c[mt][nt][2] = __expf(c[mt][nt][2] - mx2); s2 += c[mt][nt][2];
            c[mt][nt][3] = __expf(c[mt][nt][3] - mx2); s2 += c[mt][nt][3];
        }
        s1 += __shfl_xor_sync(0xffffffffu, s1, 1);
        s1 += __shfl_xor_sync(0xffffffffu, s1, 2);
        s2 += __shfl_xor_sync(0xffffffffu, s2, 1);
        s2 += __shfl_xor_sync(0xffffffffu, s2, 2);
        i1[mt] = 1.f / s1; i2[mt] = 1.f / s2;
    }

    uint32_t p[2][4][4];
    #pragma unroll
    for (int mt = 0; mt < 2; ++mt)
        #pragma unroll
        for (int kt = 0; kt < 4; ++kt) {
            __half2 h0 = __floats2half2_rn(c[mt][2*kt  ][0] * i1[mt], c[mt][2*kt  ][1] * i1[mt]);
            __half2 h1 = __floats2half2_rn(c[mt][2*kt  ][2] * i2[mt], c[mt][2*kt  ][3] * i2[mt]);
            __half2 h2 = __floats2half2_rn(c[mt][2*kt+1][0] * i1[mt], c[mt][2*kt+1][1] * i1[mt]);
            __half2 h3 = __floats2half2_rn(c[mt][2*kt+1][2] * i2[mt], c[mt][2*kt+1][3] * i2[mt]);
            p[mt][kt][0] = *(uint32_t*)&h0; p[mt][kt][1] = *(uint32_t*)&h1;
            p[mt][kt][2] = *(uint32_t*)&h2; p[mt][kt][3] = *(uint32_t*)&h3;
        }

    float o[2][4][4] = {};
    #pragma unroll
    for (int kt = 0; kt < 4; ++kt) {
        uint32_t vf[4][2];
        #pragma unroll
        for (int g = 0; g < 2; ++g) {
            int m = lane >> 3;
            uint32_t va = smem_u32(&Vs[(w64 + 16 * kt + (lane & 7) + 8 * (m & 1)) * ASTR
                                       + hc + 16 * g + 8 * (m >> 1)]);
            ldsm4t(vf[2*g][0], vf[2*g][1], vf[2*g+1][0], vf[2*g+1][1], va);
        }
        #pragma unroll
        for (int mt = 0; mt < 2; ++mt)
            #pragma unroll
            for (int nt = 0; nt < 4; ++nt)
                mma16816(o[mt][nt], p[mt][kt], vf[nt]);
    }

    #pragma unroll
    for (int mt = 0; mt < 2; ++mt) {
        int r1 = rbase + 16 * mt + (lane >> 2), r2 = r1 + 8;
        #pragma unroll
        for (int nt = 0; nt < 4; ++nt) {
            int cc = hc + 8 * nt + 2 * (lane & 3);
            *(__half2*)&Qs[r1 * ASTR + cc] = __floats2half2_rn(o[mt][nt][0], o[mt][nt][1]);
            *(__half2*)&Qs[r2 * ASTR + cc] = __floats2half2_rn(o[mt][nt][2], o[mt][nt][3]);
        }
    }
}

// ---------------------------------------------------------------------------
// The fused kernel. grid(1024), 384 threads (12 warps: 4m x 3n of 32x32).
// smem (halves): Qs@0, Ks@25600, Vs@51200, Bs@76800 (96x200), rel@96000.
// ---------------------------------------------------------------------------
#define SM_K 25600
#define SM_V 51200
#define SM_B 76800
#define SM_R 96000
#define FUSED_SMEM (96000 * 2 + 5400)

__global__ __launch_bounds__(384, 1)
void fused_kernel(const float* __restrict__ xin, const float* __restrict__ bin,
                  const float* __restrict__ b_qkv, const float* __restrict__ b_qkv_b,
                  const float* __restrict__ rel, const float* __restrict__ b_out,
                  float* __restrict__ out)
{
    extern __shared__ __half sm[];
    __half* Qs  = sm;
    __half* Ks  = sm + SM_K;
    __half* Vs  = sm + SM_V;
    __half* Bsm = sm + SM_B;
    float*  rel_s = (float*)(sm + SM_R);

    const int tid = threadIdx.x, warp = tid >> 5, lane = tid & 31;
    const int m0 = blockIdx.x * 128;
    const int wm = (warp / 3) * 32;
    const int wn = (warp % 3) * 32;

    const __half* W[8] = {
        gw_qkv + (size_t)192 * C, gw_qkv + (size_t)288 * C,
        gw_qkv + (size_t)384 * C, gw_qkv + (size_t)480 * C,
        gw_qkvb, gw_qkvb + (size_t)96 * C,
        gw_out,  gw_out  + (size_t)96 * C };

    uint4 pf[6];

    for (int i = tid; i < 1350; i += 384) rel_s[i] = rel[i];

    // ---- stage x (independent of prep), then wait for prep's weights ----
    stage_input(xin, Qs, m0, tid);
#if __CUDA_ARCH__ >= 900
    cudaGridDependencySynchronize();
#endif
    pf_load(pf, W[0], tid);
    __syncthreads();

    // ---- K, V (4 groups of 96) ----
    #pragma unroll
    for (int s = 0; s < 4; ++s) {
        pf_store(Bsm, pf, tid);
        __syncthreads();
        pf_load(pf, W[s + 1], tid);             // overlaps gemm below
        float acc[2][4][4] = {};
        gemm_group(Qs, Bsm, lane, wm, wn, acc);
        epi_smem((s < 2) ? Ks : Vs, (s & 1) * 96,
                 b_qkv + 192 + s * 96, lane, wm, wn, acc);
        __syncthreads();
    }

    // ---- stage b, compute Q (fp16-parked, in-place store after sync) ----
    stage_input(bin, Qs, m0, tid);
    __syncthreads();
    {
        uint32_t parkA[16], parkB[16];
        pf_store(Bsm, pf, tid);                 // W4 = Q0
        __syncthreads();
        pf_load(pf, W[5], tid);
        {
            float acc[2][4][4] = {};
            gemm_group(Qs, Bsm, lane, wm, wn, acc);
            epi_park(parkA, b_qkv_b, lane, wn, acc);
        }
        __syncthreads();
        pf_store(Bsm, pf, tid);                 // W5 = Q1
        __syncthreads();
        pf_load(pf, W[6], tid);
        {
            float acc[2][4][4] = {};
            gemm_group(Qs, Bsm, lane, wm, wn, acc);
            epi_park(parkB, b_qkv_b + 96, lane, wn, acc);
        }
        __syncthreads();                        // all Qs(b) reads done
        epi_unpark(Qs, 0,  lane, wm, wn, parkA);
        epi_unpark(Qs, 96, lane, wm, wn, parkB);
    }
    __syncthreads();

    // ---- attention: 24 tasks (2 win x 6 heads x 2 row-halves), 12 warps ----
    {
        const int gw0 = blockIdx.x * 2;
        #pragma unroll
        for (int task = warp; task < 24; task += 12) {
            int pair = task >> 1, rt = task & 1;
            int win  = (pair >= 6) ? 1 : 0;
            int head = pair - win * 6;
            int wimg = (gw0 + win) & 1023;
            attn_task32(Qs, Ks, Vs, rel_s + head * 225, win * 64, head * 32, rt,
                        (wimg >> 5) == 31, (wimg & 31) == 31, lane);
        }
    }

    // ---- output projection + scatter ----
    int orow[2][2];
    #pragma unroll
    for (int mt = 0; mt < 2; ++mt) {
        int r0 = m0 + wm + 16 * mt + (lane >> 2);
        orow[mt][0] = tok_to_pix_row(r0);
        orow[mt][1] = tok_to_pix_row(r0 + 8);
    }
    #pragma unroll
    for (int g = 0; g < 2; ++g) {
        pf_store(Bsm, pf, tid);                 // W6 / W7
        __syncthreads();                        // O visible + B ready
        if (g == 0) pf_load(pf, W[7], tid);
        float acc[2][4][4] = {};
        gemm_group(Qs, Bsm, lane, wm, wn, acc);
        #pragma unroll
        for (int nt = 0; nt < 4; ++nt) {
            int colg = g * 96 + wn + 8 * nt + 2 * (lane & 3);
            float b0 = b_out[colg], b1 = b_out[colg + 1];
            #pragma unroll
            for (int mt = 0; mt < 2; ++mt) {
                *(float2*)(out + orow[mt][0] + colg) =
                    make_float2(acc[mt][nt][0] + b0, acc[mt][nt][1] + b1);
                *(float2*)(out + orow[mt][1] + colg) =
                    make_float2(acc[mt][nt][2] + b0, acc[mt][nt][3] + b1);
            }
        }
        __syncthreads();                        // Bsm reads done before next store
    }
}

// ---------------------------------------------------------------------------
extern "C" void kernel_launch(void* const* d_in, const int* in_sizes, int n_in,
                              void* d_out, int out_size)
{
    const float* x        = (const float*)d_in[0];
    const float* b        = (const float*)d_in[1];
    const float* w_qkv    = (const float*)d_in[2];
    const float* b_qkv    = (const float*)d_in[3];
    const float* w_qkv_b  = (const float*)d_in[4];
    const float* b_qkv_b  = (const float*)d_in[5];
    const float* rel      = (const float*)d_in[6];
    const float* w_out    = (const float*)d_in[7];
    const float* b_out    = (const float*)d_in[8];
    float* out = (float*)d_out;

    cudaFuncSetAttribute(fused_kernel, cudaFuncAttributeMaxDynamicSharedMemorySize,
                         FUSED_SMEM);

    prep_kernel<<<108, 256>>>(w_qkv, w_qkv_b, w_out);

    // fused kernel with programmatic dependent launch: its prologue (input
    // staging) overlaps prep; cudaGridDependencySynchronize() gates only the
    // first converted-weight read.
    cudaLaunchConfig_t cfg = {};
    cfg.gridDim  = dim3(1024, 1, 1);
    cfg.blockDim = dim3(384, 1, 1);
    cfg.dynamicSmemBytes = FUSED_SMEM;
    cfg.stream = 0;
    cudaLaunchAttribute attrs[1];
    attrs[0].id = cudaLaunchAttributeProgrammaticStreamSerialization;
    attrs[0].val.programmaticStreamSerializationAllowed = 1;
    cfg.attrs = attrs;
    cfg.numAttrs = 1;
    cudaLaunchKernelEx(&cfg, fused_kernel, x, b, b_qkv, b_qkv_b, rel, b_out, out);
}